// round 13
// baseline (speedup 1.0000x reference)
#include <cuda_runtime.h>
#include <cuda_fp16.h>
#include <cstdint>

// Fused int4 group-dequant + GEMM via single-product fp16 mma.sync.
// Round 13: R10 GEMM shell (128x128, 8 warps 64x32, 3-stage cp.async A,
// 2 CTA/SM — measured at the sm_103 legacy-HMMA issue wall ~12.4cyc/mma).
// W is now dequantized INSIDE the GEMM: packed int4 LDG prefetched before
// the mma loop, LOP3/PRMT/HFMA2 dequant + STS after it (latency hidden
// behind compute). Pre-pass is X-only; W fp16 scratch eliminated.

namespace {

constexpr int MMAX = 8192, KMAX = 4096;

__device__ __half g_X[(size_t)MMAX * KMAX];

constexpr int BM = 128, BN = 128, BK = 64;
constexpr int THREADS = 256;
constexpr int ROWB = 144;                 // 64 fp16 = 128B + 16B pad
constexpr int A_OFF = 0;
constexpr int B_OFF = BM * ROWB;          // 18432
constexpr int STAGE = B_OFF + BN * ROWB;  // 36864
constexpr int SMEM_TOTAL = 3 * STAGE;     // 110592 -> 2 CTAs/SM

__device__ __forceinline__ uint32_t smem_u32(const void* p) {
    uint32_t a;
    asm("{ .reg .u64 t; cvta.to.shared.u64 t, %1; cvt.u32.u64 %0, t; }"
        : "=r"(a) : "l"(p));
    return a;
}
__device__ __forceinline__ void cp16(uint32_t dst, const void* src) {
    asm volatile("cp.async.cg.shared.global [%0], [%1], 16;"
                 :: "r"(dst), "l"(src) : "memory");
}
#define CP_COMMIT() asm volatile("cp.async.commit_group;" ::: "memory")
#define CP_WAIT(n)  asm volatile("cp.async.wait_group %0;" :: "n"(n) : "memory")

__device__ __forceinline__ void ldsm_x4(uint32_t* r, uint32_t addr) {
    asm volatile("ldmatrix.sync.aligned.m8n8.x4.shared.b16 {%0,%1,%2,%3}, [%4];"
                 : "=r"(r[0]), "=r"(r[1]), "=r"(r[2]), "=r"(r[3]) : "r"(addr));
}
__device__ __forceinline__ void mma_fp16(float* c, const uint32_t* a,
                                         const uint32_t* b) {
    asm volatile(
        "mma.sync.aligned.m16n8k16.row.col.f32.f16.f16.f32 "
        "{%0,%1,%2,%3}, {%4,%5,%6,%7}, {%8,%9}, {%0,%1,%2,%3};"
        : "+f"(c[0]), "+f"(c[1]), "+f"(c[2]), "+f"(c[3])
        : "r"(a[0]), "r"(a[1]), "r"(a[2]), "r"(a[3]), "r"(b[0]), "r"(b[1]));
}

// dequant one int32 (8 int4 values) -> 8 fp16 (k-order) -> STS.128.
// q exact via (w&0x000F000F)|0x6400 = fp16(1024+q); HSUB2 1024 exact;
// r = q*s + c_hi + c_lo, c = -s*z split in fp16 to suppress correlated
// zero-point rounding across the 128-wide group.
__device__ __forceinline__ void dq_store(uint32_t w, __half2 s2, __half2 chi,
                                         __half2 clo, uint32_t addr) {
    uint32_t h0 = ( w         & 0x000F000Fu) | 0x64006400u;  // v0, v4
    uint32_t h1 = ((w >> 4)   & 0x000F000Fu) | 0x64006400u;  // v1, v5
    uint32_t h2 = ((w >> 8)   & 0x000F000Fu) | 0x64006400u;  // v2, v6
    uint32_t h3 = ((w >> 12)  & 0x000F000Fu) | 0x64006400u;  // v3, v7
    uint32_t p0, p1, p2, p3;
    asm("prmt.b32 %0,%1,%2,0x5410;" : "=r"(p0) : "r"(h0), "r"(h1)); // v0,v1
    asm("prmt.b32 %0,%1,%2,0x5410;" : "=r"(p1) : "r"(h2), "r"(h3)); // v2,v3
    asm("prmt.b32 %0,%1,%2,0x7632;" : "=r"(p2) : "r"(h0), "r"(h1)); // v4,v5
    asm("prmt.b32 %0,%1,%2,0x7632;" : "=r"(p3) : "r"(h2), "r"(h3)); // v6,v7
    const __half2 K1024 = __half2half2(__ushort_as_half(0x6400));
    __half2 q0 = __hsub2(*reinterpret_cast<__half2*>(&p0), K1024);
    __half2 q1 = __hsub2(*reinterpret_cast<__half2*>(&p1), K1024);
    __half2 q2 = __hsub2(*reinterpret_cast<__half2*>(&p2), K1024);
    __half2 q3 = __hsub2(*reinterpret_cast<__half2*>(&p3), K1024);
    __half2 r0 = __hadd2(__hfma2(q0, s2, chi), clo);
    __half2 r1 = __hadd2(__hfma2(q1, s2, chi), clo);
    __half2 r2 = __hadd2(__hfma2(q2, s2, chi), clo);
    __half2 r3 = __hadd2(__hfma2(q3, s2, chi), clo);
    asm volatile("st.shared.v4.b32 [%0], {%1,%2,%3,%4};"
                 :: "r"(addr),
                    "r"(*reinterpret_cast<uint32_t*>(&r0)),
                    "r"(*reinterpret_cast<uint32_t*>(&r1)),
                    "r"(*reinterpret_cast<uint32_t*>(&r2)),
                    "r"(*reinterpret_cast<uint32_t*>(&r3)) : "memory");
}

// ---- pre-pass: x -> fp16 only ----
__global__ __launch_bounds__(256)
void convert_x_kernel(const float* __restrict__ X, long total8) {
    long i = (long)blockIdx.x * 256 + threadIdx.x;   // vec8 index
    if (i >= total8) return;
    const float4* src = reinterpret_cast<const float4*>(X) + 2 * i;
    float4 v0 = src[0];
    float4 v1 = src[1];
    __half2 h[4];
    h[0] = __floats2half2_rn(v0.x, v0.y);
    h[1] = __floats2half2_rn(v0.z, v0.w);
    h[2] = __floats2half2_rn(v1.x, v1.y);
    h[3] = __floats2half2_rn(v1.z, v1.w);
    reinterpret_cast<uint4*>(g_X)[i] = *reinterpret_cast<uint4*>(h);
}

// ---- main GEMM: 128x128 CTA, BK=64, 8 warps (2x4), warp tile 64x32 ----
__global__ __launch_bounds__(THREADS, 2)
void gemm_kernel(const int* __restrict__ QW, const float* __restrict__ SC,
                 const float* __restrict__ ZP, const float* __restrict__ BIAS,
                 float* __restrict__ Y, int M, int N, int K) {
    extern __shared__ char smem[];
    const uint32_t su = smem_u32(smem);
    const int tid  = threadIdx.x;
    const int lane = tid & 31;
    const int wid  = tid >> 5;
    const int bm = blockIdx.y * BM;
    const int bn = blockIdx.x * BN;
    const int mw = (wid >> 2) * 64;   // 2 warps along m
    const int nw = (wid & 3) * 32;    // 4 warps along n

    const int kWords  = K >> 3;   // int32 words per weight row
    const int nGroups = K >> 7;   // 128-wide quant groups per row

    // B loader mapping: row r = tid>>1, half-row h = tid&1 (32 k each)
    const int brow  = bn + (tid >> 1);
    const int bhalf = tid & 1;
    const int*   qrow = QW + (size_t)brow * kWords + bhalf * 4;
    const float* srow = SC + (size_t)brow * nGroups;
    const float* zrow = ZP + (size_t)brow * nGroups;
    const uint32_t b_sts = (uint32_t)(B_OFF + (tid >> 1) * ROWB + bhalf * 64);

    auto load_A = [&](int s, int t) {
        const uint32_t sb = su + s * STAGE;
        const size_t k0 = (size_t)t * BK;
#pragma unroll
        for (int j = 0; j < 4; j++) {  // A: 128 rows x 8 x 16B
            int idx = tid + j * THREADS;
            int r = idx >> 3, c = idx & 7;
            cp16(sb + A_OFF + (uint32_t)(r * ROWB + c * 16),
                 (const char*)(g_X + (size_t)(bm + r) * K + k0) + c * 16);
        }
        CP_COMMIT();
    };

    uint4  w4;
    __half2 s2, chi, clo;
    auto prefetch_B = [&](int t) {
        w4 = __ldg(reinterpret_cast<const uint4*>(qrow + t * 8));
        int g = t >> 1;   // 64-k tile within one 128-k group
        float s = __ldg(srow + g);
        float z = __ldg(zrow + g);
        float c = -s * z;
        __half sh = __float2half_rn(s);
        __half ch = __float2half_rn(c);
        __half cl = __float2half_rn(c - __half2float(ch));
        s2  = __half2half2(sh);
        chi = __half2half2(ch);
        clo = __half2half2(cl);
    };
    auto store_B = [&](int s) {
        const uint32_t base = su + s * STAGE + b_sts;
        dq_store(w4.x, s2, chi, clo, base);
        dq_store(w4.y, s2, chi, clo, base + 16);
        dq_store(w4.z, s2, chi, clo, base + 32);
        dq_store(w4.w, s2, chi, clo, base + 48);
    };

    float acc[4][4][4];
#pragma unroll
    for (int i = 0; i < 4; i++)
#pragma unroll
        for (int j = 0; j < 4; j++)
#pragma unroll
            for (int c = 0; c < 4; c++) acc[i][j][c] = 0.f;

    const int T = K / BK;  // 64

    // prologue: stages 0,1 (A via cp.async, B via inline dequant)
    load_A(0, 0);
    load_A(1, 1);
    prefetch_B(0); store_B(0);
    prefetch_B(1); store_B(1);

    // ldmatrix lane addressing
    const uint32_t a_r  = (uint32_t)((lane & 7) + ((lane >> 3) & 1) * 8);
    const uint32_t a_cb = (uint32_t)(((lane >> 4) & 1) * 16);
    const uint32_t b_r  = (uint32_t)((lane & 7) + ((lane >> 4) & 1) * 8);
    const uint32_t b_cb = (uint32_t)(((lane >> 3) & 1) * 16);

    for (int t = 0; t < T; t++) {
        // In-flight A groups: {t, t+1}; wait <=1 completes group t.
        CP_WAIT(1);
        __syncthreads();

        // Prefetch B words (LDG latency hides behind compute below) and
        // issue A cp.async for t+2 into stage (t+2)%3 == (t-1)%3, whose
        // readers all passed the barrier above.
        const bool pf = (t + 2 < T);
        if (pf) { prefetch_B(t + 2); load_A((t + 2) % 3, t + 2); }
        else    CP_COMMIT();

        const uint32_t sb = su + (t % 3) * STAGE;

#pragma unroll
        for (int kk = 0; kk < BK / 16; kk++) {
            const uint32_t kb = (uint32_t)(kk * 32);
            uint32_t a[4][4];
#pragma unroll
            for (int ms = 0; ms < 4; ms++)
                ldsm_x4(a[ms], sb + A_OFF
                               + (uint32_t)(mw + ms * 16 + a_r) * ROWB + kb + a_cb);
            uint32_t b[2][4];
#pragma unroll
            for (int ns = 0; ns < 2; ns++)
                ldsm_x4(b[ns], sb + B_OFF
                               + (uint32_t)(nw + ns * 16 + b_r) * ROWB + kb + b_cb);
#pragma unroll
            for (int ms = 0; ms < 4; ms++)
#pragma unroll
                for (int n8 = 0; n8 < 4; n8++)
                    mma_fp16(acc[ms][n8], a[ms], &b[n8 >> 1][(n8 & 1) * 2]);
        }

        // dequant + STS for t+2 after compute; visible to all warps via
        // the barrier at the top of iteration t+1 (< first read at t+2).
        if (pf) store_B((t + 2) % 3);
    }

    // epilogue: fused bias, float2 stores
#pragma unroll
    for (int n8 = 0; n8 < 4; n8++) {
        const int n0 = bn + nw + n8 * 8 + 2 * (lane & 3);
        const float bv0 = BIAS[n0];
        const float bv1 = BIAS[n0 + 1];
#pragma unroll
        for (int ms = 0; ms < 4; ms++) {
            const int m0 = bm + mw + ms * 16 + (lane >> 2);
            float2 v;
            v.x = acc[ms][n8][0] + bv0;
            v.y = acc[ms][n8][1] + bv1;
            *reinterpret_cast<float2*>(Y + (size_t)m0 * N + n0) = v;
            v.x = acc[ms][n8][2] + bv0;
            v.y = acc[ms][n8][3] + bv1;
            *reinterpret_cast<float2*>(Y + (size_t)(m0 + 8) * N + n0) = v;
        }
    }
}

}  // namespace

extern "C" void kernel_launch(void* const* d_in, const int* in_sizes, int n_in,
                              void* d_out, int out_size) {
    const float* x    = (const float*)d_in[0];
    const int*   qw   = (const int*)d_in[1];
    const float* sc   = (const float*)d_in[2];
    const float* zp   = (const float*)d_in[3];
    const float* bias = (const float*)d_in[4];
    float* y = (float*)d_out;

    const int N = in_sizes[4];
    const long long K = ((long long)in_sizes[1] * 8) / N;
    const long long M = (long long)in_sizes[0] / K;

    cudaFuncSetAttribute(gemm_kernel, cudaFuncAttributeMaxDynamicSharedMemorySize,
                         SMEM_TOTAL);

    {   // pre-pass: x -> fp16 only (W handled inside the GEMM)
        long total8 = (long)M * K / 8;
        int blocks = (int)((total8 + 255) / 256);
        convert_x_kernel<<<blocks, 256>>>(x, total8);
    }
    {
        dim3 grid((unsigned)(N / BN), (unsigned)(M / BM));
        gemm_kernel<<<grid, THREADS, SMEM_TOTAL>>>(qw, sc, zp, bias, y,
                                                   (int)M, N, (int)K);
    }
}

// round 15
// speedup vs baseline: 1.0254x; 1.0254x over previous
#include <cuda_runtime.h>
#include <cuda_fp16.h>
#include <cstdint>

// Fused int4 group-dequant + GEMM, Marlin-style (round 15 = round 14 with the
// scale-rounding bug fixed): B moves global->smem->regs PACKED int4, register
// dequant via |0x6400 trick; the correction constant now cancels the ROUNDED
// fp16 scale: c'' = -(1024*float(s_h) + s*z), killing the 1039*(s_h-s) bias
// that failed round 14 (3.5e-2). Residual error = q*(s_h-s) + 1 fma rounding,
// same structure round 13 measured at 4.4e-4.
// GEMM shell = round-10 champion: 128x128 tile, 8 warps 64x32, 3-stage
// cp.async, 2 CTA/SM.

namespace {

constexpr int MMAX = 8192, NMAX = 4096, KMAX = 4096;

__device__ __half g_X[(size_t)MMAX * KMAX];
__device__ uint4  g_Wp[(size_t)(NMAX / 128) * (KMAX / 64) * 256];  // 8 MB

constexpr int BM = 128, BN = 128, BK = 64;
constexpr int THREADS = 256;
constexpr int ROWB = 144;                  // A row: 64 fp16 = 128B + 16B pad
constexpr int A_OFF = 0;
constexpr int B4_OFF = BM * ROWB;          // 18432
constexpr int STAGE = B4_OFF + 4096;       // packed B tile = 4KB -> 22528
constexpr int SMEM_TOTAL = 3 * STAGE;      // 67584 -> 2 CTAs/SM

__device__ __forceinline__ uint32_t smem_u32(const void* p) {
    uint32_t a;
    asm("{ .reg .u64 t; cvta.to.shared.u64 t, %1; cvt.u32.u64 %0, t; }"
        : "=r"(a) : "l"(p));
    return a;
}
__device__ __forceinline__ void cp16(uint32_t dst, const void* src) {
    asm volatile("cp.async.cg.shared.global [%0], [%1], 16;"
                 :: "r"(dst), "l"(src) : "memory");
}
#define CP_COMMIT() asm volatile("cp.async.commit_group;" ::: "memory")
#define CP_WAIT(n)  asm volatile("cp.async.wait_group %0;" :: "n"(n) : "memory")

__device__ __forceinline__ void ldsm_x4(uint32_t* r, uint32_t addr) {
    asm volatile("ldmatrix.sync.aligned.m8n8.x4.shared.b16 {%0,%1,%2,%3}, [%4];"
                 : "=r"(r[0]), "=r"(r[1]), "=r"(r[2]), "=r"(r[3]) : "r"(addr));
}
__device__ __forceinline__ void lds128(uint32_t* r, uint32_t addr) {
    asm volatile("ld.shared.v4.b32 {%0,%1,%2,%3}, [%4];"
                 : "=r"(r[0]), "=r"(r[1]), "=r"(r[2]), "=r"(r[3]) : "r"(addr));
}
__device__ __forceinline__ void mma_fp16(float* c, const uint32_t* a,
                                         const uint32_t* b) {
    asm volatile(
        "mma.sync.aligned.m16n8k16.row.col.f32.f16.f16.f32 "
        "{%0,%1,%2,%3}, {%4,%5,%6,%7}, {%8,%9}, {%0,%1,%2,%3};"
        : "+f"(c[0]), "+f"(c[1]), "+f"(c[2]), "+f"(c[3])
        : "r"(a[0]), "r"(a[1]), "r"(a[2]), "r"(a[3]), "r"(b[0]), "r"(b[1]));
}

// ---- merged pre-pass: X->fp16 (blocks [0,xBlocks)) + W repack (rest) ----
// Repack unit (16 bits) for GEMM thread (nwg,lane), n8-block j, k-step kk:
//   nibbles [k0,k1,k2,k3] = B[n][kbase+2m], +1, +8, +9  (m = lane&3)
//   n = nblk*128 + nwg*32 + 8j + (lane>>2), kbase = T*64 + kk*16.
// uint4 layout per tile: index (nwg*2 + which)*32 + lane; words within
// uint4: [kl*2 + (j>>1)], halves j&1 (kl = kk&1, which = kk>>1).
__global__ __launch_bounds__(256)
void prepass_kernel(const float* __restrict__ X,
                    const int*   __restrict__ QW,
                    int xBlocks, int kWords, int KT, long xTotal8) {
    if ((int)blockIdx.x < xBlocks) {
        long i = (long)blockIdx.x * 256 + threadIdx.x;
        if (i >= xTotal8) return;
        const float4* src = reinterpret_cast<const float4*>(X) + 2 * i;
        float4 v0 = src[0];
        float4 v1 = src[1];
        __half2 h[4];
        h[0] = __floats2half2_rn(v0.x, v0.y);
        h[1] = __floats2half2_rn(v0.z, v0.w);
        h[2] = __floats2half2_rn(v1.x, v1.y);
        h[3] = __floats2half2_rn(v1.z, v1.w);
        reinterpret_cast<uint4*>(g_X)[i] = *reinterpret_cast<uint4*>(h);
    } else {
        long idx = (long)((int)blockIdx.x - xBlocks) * 256 + threadIdx.x;
        int lane  = (int)(idx & 31);
        int which = (int)((idx >> 5) & 1);
        int nwg   = (int)((idx >> 6) & 3);
        long rest = idx >> 8;
        int T    = (int)(rest % KT);
        int nblk = (int)(rest / KT);
        int m = lane & 3;
        uint32_t out[4];
#pragma unroll
        for (int kl = 0; kl < 2; kl++) {
            int kk = which * 2 + kl;
            int W0 = T * 8 + kk * 2;
#pragma unroll
            for (int j = 0; j < 4; j++) {
                int n = nblk * 128 + nwg * 32 + 8 * j + (lane >> 2);
                uint32_t w0 = (uint32_t)QW[(size_t)n * kWords + W0];
                uint32_t w1 = (uint32_t)QW[(size_t)n * kWords + W0 + 1];
                uint32_t u = ((w0 >> (8 * m)) & 0xFFu)
                           | (((w1 >> (8 * m)) & 0xFFu) << 8);
                if (j & 1) out[kl * 2 + (j >> 1)] |= u << 16;
                else       out[kl * 2 + (j >> 1)]  = u;
            }
        }
        g_Wp[idx] = make_uint4(out[0], out[1], out[2], out[3]);
    }
}

// ---- main GEMM: 128x128 CTA, BK=64, 8 warps (2x4), warp tile 64x32 ----
__global__ __launch_bounds__(THREADS, 2)
void gemm_kernel(const float* __restrict__ SC, const float* __restrict__ ZP,
                 const float* __restrict__ BIAS, float* __restrict__ Y,
                 int M, int N, int K) {
    extern __shared__ char smem[];
    const uint32_t su = smem_u32(smem);
    const int tid  = threadIdx.x;
    const int lane = tid & 31;
    const int wid  = tid >> 5;
    const int bm = blockIdx.y * BM;
    const int bn = blockIdx.x * BN;
    const int mw = (wid >> 2) * 64;   // 2 warps along m
    const int nw = (wid & 3) * 32;    // 4 warps along n
    const int nwg = wid & 3;

    const int KT = K / 64;
    const int nG = K >> 7;            // 128-wide groups
    const int nbase = bn + nwg * 32 + (lane >> 2);

    const uint4* wp_tile0 = g_Wp + (size_t)(bn >> 7) * KT * 256 + tid;

    auto load_stage = [&](int s, int t) {
        const uint32_t sb = su + s * STAGE;
        const size_t k0 = (size_t)t * BK;
#pragma unroll
        for (int j = 0; j < 4; j++) {  // A: 128 rows x 8 x 16B
            int idx = tid + j * THREADS;
            int r = idx >> 3, c = idx & 7;
            cp16(sb + A_OFF + (uint32_t)(r * ROWB + c * 16),
                 (const char*)(g_X + (size_t)(bm + r) * K + k0) + c * 16);
        }
        // B: packed int4 fragment-order tile, 4KB, 1 cp16/thread
        cp16(sb + B4_OFF + (uint32_t)(tid * 16), wp_tile0 + (size_t)t * 256);
        CP_COMMIT();
    };

    // scale state: cur (converted half2) + nxt (raw floats)
    __half2 s2c[4], ch2[4], cl2[4];
    float sn[4], cn[4];
    auto ldg_scales = [&](int g) {
#pragma unroll
        for (int j = 0; j < 4; j++) {
            int n = nbase + 8 * j;
            float s = __ldg(SC + (size_t)n * nG + g);
            float z = __ldg(ZP + (size_t)n * nG + g);
            sn[j] = s;
            // FIX vs round 14: cancel the ROUNDED fp16 scale's 1024-bias.
            // (1024+q)*s_h + c'' = q*s_h - s*z exactly up to one fma rounding.
            float s_h = __half2float(__float2half_rn(s));
            cn[j] = -(1024.f * s_h + s * z);
        }
    };
    auto cvt_scales = [&]() {
#pragma unroll
        for (int j = 0; j < 4; j++) {
            __half sh = __float2half_rn(sn[j]);
            __half ch = __float2half_rn(cn[j]);
            __half cl = __float2half_rn(cn[j] - __half2float(ch));
            s2c[j] = __half2half2(sh);
            ch2[j] = __half2half2(ch);
            cl2[j] = __half2half2(cl);
        }
    };

    float acc[4][4][4];
#pragma unroll
    for (int i = 0; i < 4; i++)
#pragma unroll
        for (int j = 0; j < 4; j++)
#pragma unroll
            for (int c = 0; c < 4; c++) acc[i][j][c] = 0.f;

    const int T = K / BK;  // 64
    load_stage(0, 0);
    load_stage(1, 1);
    ldg_scales(0);
    cvt_scales();
    if (nG > 1) ldg_scales(1);

    // ldmatrix lane addressing (A unchanged)
    const uint32_t a_r  = (uint32_t)((lane & 7) + ((lane >> 3) & 1) * 8);
    const uint32_t a_cb = (uint32_t)(((lane >> 4) & 1) * 16);
    const uint32_t b_ld0 = (uint32_t)(B4_OFF + ((nwg * 2 + 0) * 32 + lane) * 16);
    const uint32_t b_ld1 = (uint32_t)(B4_OFF + ((nwg * 2 + 1) * 32 + lane) * 16);

    for (int t = 0; t < T; t++) {
        CP_WAIT(1);
        __syncthreads();

        // rotate scales at group boundary (group = t>>1), prefetch next
        if (t >= 2 && (t & 1) == 0) {
            cvt_scales();                      // nxt (group t/2) -> cur
            if ((t >> 1) + 1 < nG) ldg_scales((t >> 1) + 1);
        }

        if (t + 2 < T) load_stage((t + 2) % 3, t + 2);
        else           CP_COMMIT();

        const uint32_t sb = su + (t % 3) * STAGE;

        uint32_t qb[8];
        lds128(qb,     sb + b_ld0);
        lds128(qb + 4, sb + b_ld1);

#pragma unroll
        for (int kk = 0; kk < 4; kk++) {
            const uint32_t kb = (uint32_t)(kk * 32);
            uint32_t a[4][4];
#pragma unroll
            for (int ms = 0; ms < 4; ms++)
                ldsm_x4(a[ms], sb + A_OFF
                               + (uint32_t)(mw + ms * 16 + a_r) * ROWB + kb + a_cb);
#pragma unroll
            for (int j = 0; j < 4; j++) {
                const uint32_t w = qb[(kk >> 1) * 4 + (kk & 1) * 2 + (j >> 1)];
                uint32_t B0, B1;
                if ((j & 1) == 0) {
                    B0 = (w & 0x0000000Fu) | ((w << 12) & 0x000F0000u) | 0x64006400u;
                    B1 = ((w >> 8) & 0x0000000Fu) | ((w << 4) & 0x000F0000u) | 0x64006400u;
                } else {
                    B0 = ((w >> 16) & 0x0000000Fu) | ((w >> 4) & 0x000F0000u) | 0x64006400u;
                    B1 = ((w >> 24) & 0x0000000Fu) | ((w >> 12) & 0x000F0000u) | 0x64006400u;
                }
                __half2 q0 = *reinterpret_cast<__half2*>(&B0);   // 1024+q
                __half2 q1 = *reinterpret_cast<__half2*>(&B1);
                __half2 v0 = __hadd2(__hfma2(q0, s2c[j], ch2[j]), cl2[j]);
                __half2 v1 = __hadd2(__hfma2(q1, s2c[j], ch2[j]), cl2[j]);
                uint32_t bf[2] = {*reinterpret_cast<uint32_t*>(&v0),
                                  *reinterpret_cast<uint32_t*>(&v1)};
#pragma unroll
                for (int ms = 0; ms < 4; ms++)
                    mma_fp16(acc[ms][j], a[ms], bf);
            }
        }
    }

    // epilogue: fused bias, float2 stores
#pragma unroll
    for (int j = 0; j < 4; j++) {
        const int n0 = bn + nw + j * 8 + 2 * (lane & 3);
        const float bv0 = BIAS[n0];
        const float bv1 = BIAS[n0 + 1];
#pragma unroll
        for (int ms = 0; ms < 4; ms++) {
            const int m0 = bm + mw + ms * 16 + (lane >> 2);
            float2 v;
            v.x = acc[ms][j][0] + bv0;
            v.y = acc[ms][j][1] + bv1;
            *reinterpret_cast<float2*>(Y + (size_t)m0 * N + n0) = v;
            v.x = acc[ms][j][2] + bv0;
            v.y = acc[ms][j][3] + bv1;
            *reinterpret_cast<float2*>(Y + (size_t)(m0 + 8) * N + n0) = v;
        }
    }
}

}  // namespace

extern "C" void kernel_launch(void* const* d_in, const int* in_sizes, int n_in,
                              void* d_out, int out_size) {
    const float* x    = (const float*)d_in[0];
    const int*   qw   = (const int*)d_in[1];
    const float* sc   = (const float*)d_in[2];
    const float* zp   = (const float*)d_in[3];
    const float* bias = (const float*)d_in[4];
    float* y = (float*)d_out;

    const int N = in_sizes[4];
    const long long K = ((long long)in_sizes[1] * 8) / N;
    const long long M = (long long)in_sizes[0] / K;
    const int KT = (int)(K / 64);
    const int kWords = (int)(K >> 3);

    cudaFuncSetAttribute(gemm_kernel, cudaFuncAttributeMaxDynamicSharedMemorySize,
                         SMEM_TOTAL);

    {   // merged pre-pass: X->fp16 + W fragment-order repack
        long xTotal8 = (long)M * K / 8;
        int  xBlocks = (int)((xTotal8 + 255) / 256);
        long wTotal  = (long)(N / 128) * KT * 256;     // uint4 count
        int  wBlocks = (int)((wTotal + 255) / 256);
        prepass_kernel<<<xBlocks + wBlocks, 256>>>(x, qw, xBlocks, kWords, KT,
                                                   xTotal8);
    }
    {
        dim3 grid((unsigned)(N / BN), (unsigned)(M / BM));
        gemm_kernel<<<grid, THREADS, SMEM_TOTAL>>>(sc, zp, bias, y,
                                                   (int)M, N, (int)K);
    }
}

// round 16
// speedup vs baseline: 1.2283x; 1.1979x over previous
#include <cuda_runtime.h>
#include <cuda_fp16.h>
#include <cstdint>

// Fused int4 group-dequant + GEMM via single-product fp16 mma.sync.
// Round 16: restore the round-10 champion GEMM exactly (128x128 tile,
// 8 warps 64x32, 3-stage cp.async, 2 CTA/SM — measured best overlap of the
// sm_103 legacy-HMMA pipe at ~61% duty; all dequant-in-GEMM and tile-shape
// alternatives regressed). Micro-wins only: B-ldsm issued before A-ldsm,
// and a streaming (__stwt) grid-stride convert pre-pass.

namespace {

constexpr int MMAX = 8192, NMAX = 4096, KMAX = 4096;

__device__ __half g_X[(size_t)MMAX * KMAX];
__device__ __half g_W[(size_t)NMAX * KMAX];

constexpr int BM = 128, BN = 128, BK = 64;
constexpr int THREADS = 256;
constexpr int ROWB = 144;                 // 64 fp16 = 128B + 16B pad
constexpr int A_OFF = 0;
constexpr int B_OFF = BM * ROWB;          // 18432
constexpr int STAGE = B_OFF + BN * ROWB;  // 36864
constexpr int SMEM_TOTAL = 3 * STAGE;     // 110592 -> 2 CTAs/SM

__device__ __forceinline__ uint32_t smem_u32(const void* p) {
    uint32_t a;
    asm("{ .reg .u64 t; cvta.to.shared.u64 t, %1; cvt.u32.u64 %0, t; }"
        : "=r"(a) : "l"(p));
    return a;
}
__device__ __forceinline__ void cp16(uint32_t dst, const void* src) {
    asm volatile("cp.async.cg.shared.global [%0], [%1], 16;"
                 :: "r"(dst), "l"(src) : "memory");
}
#define CP_COMMIT() asm volatile("cp.async.commit_group;" ::: "memory")
#define CP_WAIT(n)  asm volatile("cp.async.wait_group %0;" :: "n"(n) : "memory")

__device__ __forceinline__ void ldsm_x4(uint32_t* r, uint32_t addr) {
    asm volatile("ldmatrix.sync.aligned.m8n8.x4.shared.b16 {%0,%1,%2,%3}, [%4];"
                 : "=r"(r[0]), "=r"(r[1]), "=r"(r[2]), "=r"(r[3]) : "r"(addr));
}
__device__ __forceinline__ void mma_fp16(float* c, const uint32_t* a,
                                         const uint32_t* b) {
    asm volatile(
        "mma.sync.aligned.m16n8k16.row.col.f32.f16.f16.f32 "
        "{%0,%1,%2,%3}, {%4,%5,%6,%7}, {%8,%9}, {%0,%1,%2,%3};"
        : "+f"(c[0]), "+f"(c[1]), "+f"(c[2]), "+f"(c[3])
        : "r"(a[0]), "r"(a[1]), "r"(a[2]), "r"(a[3]), "r"(b[0]), "r"(b[1]));
}
__device__ __forceinline__ void stwt16(void* dst, uint4 v) {
    asm volatile("st.global.wt.v4.b32 [%0], {%1,%2,%3,%4};"
                 :: "l"(dst), "r"(v.x), "r"(v.y), "r"(v.z), "r"(v.w) : "memory");
}

// ---- merged streaming pre-pass ----
// Blocks [0, xBlocks):           x -> fp16, 2 vec8 per thread, __stwt
// Blocks [xBlocks, xBlocks+wB):  dequant W -> fp16 (2 words in / 32B out)
__global__ __launch_bounds__(256)
void convert_kernel(const float* __restrict__ X,
                    const int*   __restrict__ QW,
                    const float* __restrict__ SC,
                    const float* __restrict__ ZP,
                    int xBlocks, int wordsPerRow, int nGroups, long xTotal8) {
    if ((int)blockIdx.x < xBlocks) {
        long i0 = (long)blockIdx.x * 512 + threadIdx.x;
#pragma unroll
        for (int r = 0; r < 2; r++) {
            long i = i0 + r * 256;
            if (i >= xTotal8) break;
            const float4* src = reinterpret_cast<const float4*>(X) + 2 * i;
            float4 v0 = src[0];
            float4 v1 = src[1];
            __half2 h[4];
            h[0] = __floats2half2_rn(v0.x, v0.y);
            h[1] = __floats2half2_rn(v0.z, v0.w);
            h[2] = __floats2half2_rn(v1.x, v1.y);
            h[3] = __floats2half2_rn(v1.z, v1.w);
            stwt16(reinterpret_cast<uint4*>(g_X) + i,
                   *reinterpret_cast<uint4*>(h));
        }
    } else {
        long tIdx = (long)((int)blockIdx.x - xBlocks) * 256 + threadIdx.x;
        long j = 2 * tIdx;                    // first word index
        int n = (int)(j / wordsPerRow);
        int w = (int)(j % wordsPerRow);
        int g = (w * 8) >> 7;
        float s = SC[(size_t)n * nGroups + g];
        float z = ZP[(size_t)n * nGroups + g];
        float szn = -s * z;
        int2 qq = *reinterpret_cast<const int2*>(QW + j);
#pragma unroll
        for (int wd = 0; wd < 2; wd++) {
            unsigned q = (unsigned)(wd == 0 ? qq.x : qq.y);
            __half2 h[4];
#pragma unroll
            for (int k = 0; k < 4; k++) {
                float f0 = fmaf(s, (float)((q >> (8 * k)) & 0xFu), szn);
                float f1 = fmaf(s, (float)((q >> (8 * k + 4)) & 0xFu), szn);
                h[k] = __floats2half2_rn(f0, f1);
            }
            stwt16(reinterpret_cast<uint4*>(g_W) + j + wd,
                   *reinterpret_cast<uint4*>(h));
        }
    }
}

// ---- main GEMM: 128x128 CTA, BK=64, 8 warps (2x4), warp tile 64x32 ----
__global__ __launch_bounds__(THREADS, 2)
void gemm_kernel(const float* __restrict__ BIAS, float* __restrict__ Y,
                 int M, int N, int K) {
    extern __shared__ char smem[];
    const uint32_t su = smem_u32(smem);
    const int tid  = threadIdx.x;
    const int lane = tid & 31;
    const int wid  = tid >> 5;
    const int bm = blockIdx.y * BM;
    const int bn = blockIdx.x * BN;
    const int mw = (wid >> 2) * 64;   // 2 warps along m
    const int nw = (wid & 3) * 32;    // 4 warps along n

    auto load_stage = [&](int s, int t) {
        const uint32_t sb = su + s * STAGE;
        const size_t k0 = (size_t)t * BK;
#pragma unroll
        for (int j = 0; j < 4; j++) {  // A: 128 rows x 8 x 16B
            int idx = tid + j * THREADS;
            int r = idx >> 3, c = idx & 7;
            cp16(sb + A_OFF + (uint32_t)(r * ROWB + c * 16),
                 (const char*)(g_X + (size_t)(bm + r) * K + k0) + c * 16);
        }
#pragma unroll
        for (int j = 0; j < 4; j++) {  // B: 128 rows x 8 x 16B
            int idx = tid + j * THREADS;
            int r = idx >> 3, c = idx & 7;
            cp16(sb + B_OFF + (uint32_t)(r * ROWB + c * 16),
                 (const char*)(g_W + (size_t)(bn + r) * K + k0) + c * 16);
        }
        CP_COMMIT();
    };

    float acc[4][4][4];
#pragma unroll
    for (int i = 0; i < 4; i++)
#pragma unroll
        for (int j = 0; j < 4; j++)
#pragma unroll
            for (int c = 0; c < 4; c++) acc[i][j][c] = 0.f;

    const int T = K / BK;  // 64
    load_stage(0, 0);
    load_stage(1, 1);

    // ldmatrix lane addressing
    const uint32_t a_r  = (uint32_t)((lane & 7) + ((lane >> 3) & 1) * 8);
    const uint32_t a_cb = (uint32_t)(((lane >> 4) & 1) * 16);
    const uint32_t b_r  = (uint32_t)((lane & 7) + ((lane >> 4) & 1) * 8);
    const uint32_t b_cb = (uint32_t)(((lane >> 3) & 1) * 16);

    for (int t = 0; t < T; t++) {
        // In-flight groups: {t, t+1}; wait <=1 completes group t.
        CP_WAIT(1);
        __syncthreads();

        // Issue load(t+2) into stage (t+2)%3 == (t-1)%3, whose readers all
        // passed the barrier above. Empty commits keep depth uniform.
        if (t + 2 < T) load_stage((t + 2) % 3, t + 2);
        else           CP_COMMIT();

        const uint32_t sb = su + (t % 3) * STAGE;

#pragma unroll
        for (int kk = 0; kk < BK / 16; kk++) {
            const uint32_t kb = (uint32_t)(kk * 32);
            // B ldsm first: feeds the first mma, earlier issue hides latency
            uint32_t b[2][4];
#pragma unroll
            for (int ns = 0; ns < 2; ns++)
                ldsm_x4(b[ns], sb + B_OFF
                               + (uint32_t)(nw + ns * 16 + b_r) * ROWB + kb + b_cb);
            uint32_t a[4][4];
#pragma unroll
            for (int ms = 0; ms < 4; ms++)
                ldsm_x4(a[ms], sb + A_OFF
                               + (uint32_t)(mw + ms * 16 + a_r) * ROWB + kb + a_cb);
#pragma unroll
            for (int ms = 0; ms < 4; ms++)
#pragma unroll
                for (int n8 = 0; n8 < 4; n8++)
                    mma_fp16(acc[ms][n8], a[ms], &b[n8 >> 1][(n8 & 1) * 2]);
        }
    }

    // epilogue: fused bias, float2 stores
#pragma unroll
    for (int n8 = 0; n8 < 4; n8++) {
        const int n0 = bn + nw + n8 * 8 + 2 * (lane & 3);
        const float bv0 = BIAS[n0];
        const float bv1 = BIAS[n0 + 1];
#pragma unroll
        for (int ms = 0; ms < 4; ms++) {
            const int m0 = bm + mw + ms * 16 + (lane >> 2);
            float2 v;
            v.x = acc[ms][n8][0] + bv0;
            v.y = acc[ms][n8][1] + bv1;
            *reinterpret_cast<float2*>(Y + (size_t)m0 * N + n0) = v;
            v.x = acc[ms][n8][2] + bv0;
            v.y = acc[ms][n8][3] + bv1;
            *reinterpret_cast<float2*>(Y + (size_t)(m0 + 8) * N + n0) = v;
        }
    }
}

}  // namespace

extern "C" void kernel_launch(void* const* d_in, const int* in_sizes, int n_in,
                              void* d_out, int out_size) {
    const float* x    = (const float*)d_in[0];
    const int*   qw   = (const int*)d_in[1];
    const float* sc   = (const float*)d_in[2];
    const float* zp   = (const float*)d_in[3];
    const float* bias = (const float*)d_in[4];
    float* y = (float*)d_out;

    const int N = in_sizes[4];
    const long long K = ((long long)in_sizes[1] * 8) / N;
    const long long M = (long long)in_sizes[0] / K;

    cudaFuncSetAttribute(gemm_kernel, cudaFuncAttributeMaxDynamicSharedMemorySize,
                         SMEM_TOTAL);

    {   // merged streaming pre-pass
        long xTotal8 = (long)M * K / 8;
        int  xBlocks = (int)((xTotal8 + 511) / 512);   // 2 vec8 per thread
        int  wordsPerRow = (int)(K / 8);
        int  nGroups     = (int)(K / 128);
        long wPairs  = (long)N * wordsPerRow / 2;
        int  wBlocks = (int)((wPairs + 255) / 256);
        convert_kernel<<<xBlocks + wBlocks, 256>>>(x, qw, sc, zp, xBlocks,
                                                   wordsPerRow, nGroups, xTotal8);
    }
    {
        dim3 grid((unsigned)(N / BN), (unsigned)(M / BM));
        gemm_kernel<<<grid, THREADS, SMEM_TOTAL>>>(bias, y, (int)M, N, (int)K);
    }
}